// round 4
// baseline (speedup 1.0000x reference)
#include <cuda_runtime.h>
#include <cstdint>

#define NN 50000
#define EE 800000
#define ETOT (EE + NN)
#define DD 128
#define NBSCAN ((NN + 1023) / 1024)

// ---------------- static device scratch ----------------
__device__ float g_h[NN * DD];
__device__ float g_xl[NN * DD];
__device__ float g_xr[NN * DD];
__device__ int   g_deg[NN];
__device__ int   g_offs[NN + 1];
__device__ int   g_cur[NN];
__device__ int   g_srcs[ETOT];
__device__ int   g_bsums[NBSCAN];
// pre-split tf32 weights: [layer][k][col 0..255 = Wl|Wr]
__device__ uint32_t g_WH[4 * 128 * 256];
__device__ uint32_t g_WL[4 * 128 * 256];

__device__ __forceinline__ uint32_t f2tf32(float x) {
    uint32_t r;
    asm volatile("cvt.rna.tf32.f32 %0, %1;" : "=r"(r) : "f"(x));
    return r;
}

// ---------------- CSR build ----------------
__global__ void zero_counts() {
    int i = blockIdx.x * blockDim.x + threadIdx.x;
    if (i < NN) { g_deg[i] = 0; g_cur[i] = 0; }
}

__global__ void count_edges(const int* __restrict__ ei) {
    int t = blockIdx.x * blockDim.x + threadIdx.x;
    if (t < ETOT) {
        int dst = (t < EE) ? ei[EE + t] : (t - EE);
        atomicAdd(&g_deg[dst], 1);
    }
}

__global__ void scan_block() {
    __shared__ int sm[256];
    int t = threadIdx.x;
    int base = blockIdx.x * 1024 + t * 4;
    int v0 = (base + 0 < NN) ? g_deg[base + 0] : 0;
    int v1 = (base + 1 < NN) ? g_deg[base + 1] : 0;
    int v2 = (base + 2 < NN) ? g_deg[base + 2] : 0;
    int v3 = (base + 3 < NN) ? g_deg[base + 3] : 0;
    v1 += v0; v2 += v1; v3 += v2;
    sm[t] = v3;
    __syncthreads();
    #pragma unroll
    for (int off = 1; off < 256; off <<= 1) {
        int add = (t >= off) ? sm[t - off] : 0;
        __syncthreads();
        sm[t] += add;
        __syncthreads();
    }
    int prev = (t > 0) ? sm[t - 1] : 0;
    if (base + 0 < NN) g_offs[base + 0] = prev + v0;
    if (base + 1 < NN) g_offs[base + 1] = prev + v1;
    if (base + 2 < NN) g_offs[base + 2] = prev + v2;
    if (base + 3 < NN) g_offs[base + 3] = prev + v3;
    if (t == 255) g_bsums[blockIdx.x] = sm[255];
}

__global__ void scan_spine() {
    if (threadIdx.x == 0) {
        int acc = 0;
        for (int i = 0; i < NBSCAN; i++) { int v = g_bsums[i]; g_bsums[i] = acc; acc += v; }
    }
}

__global__ void scan_fix() {
    int i = blockIdx.x * blockDim.x + threadIdx.x;
    if (i < NN) g_offs[i] = g_offs[i] - g_deg[i] + g_bsums[i >> 10];
    if (i == 0) g_offs[NN] = ETOT;
}

__global__ void fill_edges(const int* __restrict__ ei) {
    int t = blockIdx.x * blockDim.x + threadIdx.x;
    if (t < ETOT) {
        int src, dst;
        if (t < EE) { src = ei[t]; dst = ei[EE + t]; }
        else        { src = t - EE; dst = src; }
        int pos = g_offs[dst] + atomicAdd(&g_cur[dst], 1);
        g_srcs[pos] = src;
    }
}

// ---------------- weight pre-split ----------------
__global__ void split_w(const float* __restrict__ Wl, const float* __restrict__ Wr) {
    int i = blockIdx.x * blockDim.x + threadIdx.x;
    if (i >= 4 * 128 * 256) return;
    int layer = i >> 15;
    int rem = i & 32767;
    int k = rem >> 8;
    int c = rem & 255;
    float v = (c < 128) ? Wl[layer * 16384 + k * 128 + c]
                        : Wr[layer * 16384 + k * 128 + (c - 128)];
    uint32_t hi = f2tf32(v);
    float lo = v - __uint_as_float(hi);
    g_WH[i] = hi;
    g_WL[i] = f2tf32(lo);
}

// ---------------- layer 0 GEMM (K=7) ----------------
__global__ void gemm0(const float* __restrict__ x,
                      const float* __restrict__ Wl0, const float* __restrict__ Wr0,
                      const float* __restrict__ bl0, const float* __restrict__ br0) {
    int node = blockIdx.x;
    int j = threadIdx.x;
    __shared__ float xs[7];
    if (j < 7) xs[j] = x[node * 7 + j];
    __syncthreads();
    const float* W = (j < 128) ? Wl0 : Wr0;
    int c = j & 127;
    float acc = (j < 128) ? bl0[c] : br0[c];
    #pragma unroll
    for (int k = 0; k < 7; k++) acc += xs[k] * W[k * 128 + c];
    if (j < 128) g_xl[node * DD + c] = acc;
    else         g_xr[node * DD + c] = acc;
}

// ---------------- TC GEMM v2: fragment-order SMEM, A=tf32, B=tf32 hi/lo ----------------
// Grid (ceil(N/128), 2): y=0 -> Wl -> g_xl, y=1 -> Wr -> g_xr.
// Block tile 128x128, 8 warps (wm 0..3, wn 0..1), warp tile 32x64 = 2 m16 x 8 n8.
#define KC 16

__device__ __forceinline__ void mma_tf32(float c[4], const uint4 a, uint32_t b0, uint32_t b1) {
    asm volatile(
        "mma.sync.aligned.m16n8k8.row.col.f32.tf32.tf32.f32 "
        "{%0,%1,%2,%3}, {%4,%5,%6,%7}, {%8,%9}, {%0,%1,%2,%3};"
        : "+f"(c[0]), "+f"(c[1]), "+f"(c[2]), "+f"(c[3])
        : "r"(a.x), "r"(a.y), "r"(a.z), "r"(a.w), "r"(b0), "r"(b1));
}

__global__ __launch_bounds__(256) void gemm_tc(int layer,
                                               const float* __restrict__ bl_,
                                               const float* __restrict__ br_) {
    // fragment-order storage: A frags [mt*2+ks][lane] uint4; B frags [nt*2+ks][lane] uint2
    __shared__ uint4 AsF[16][32];     // 8 KB
    __shared__ uint2 BsHF[32][32];    // 8 KB
    __shared__ uint2 BsLF[32][32];    // 8 KB

    int tid  = threadIdx.x;
    int lane = tid & 31;
    int wid  = tid >> 5;
    int wm   = wid >> 1;        // 0..3
    int wn   = wid & 1;         // 0..1
    int row0 = blockIdx.x * 128;
    int yhalf = blockIdx.y;

    const uint32_t* WHbase = g_WH + layer * 32768 + yhalf * 128;
    const uint32_t* WLbase = g_WL + layer * 32768 + yhalf * 128;

    float c[2][8][4];
    #pragma unroll
    for (int mi = 0; mi < 2; mi++)
        #pragma unroll
        for (int ni = 0; ni < 8; ni++)
            #pragma unroll
            for (int q = 0; q < 4; q++) c[mi][ni][q] = 0.f;

    // stage-A thread mapping
    int ar   = tid >> 1;            // row 0..127
    int aks  = tid & 1;             // k-step (k offset aks*8)
    int amt  = ar >> 4;
    int arl  = ar & 15;
    int ag   = arl & 7;
    int ahi8 = arl >> 3;
    // stage-B thread mapping
    int bk   = tid >> 4;            // k 0..15
    int bc   = (tid & 15) * 8;      // col base
    int bks  = bk >> 3;
    int bkl  = bk & 7;
    int btig = bkl & 3;
    int bkhi = bkl >> 2;
    int bnt  = bc >> 3;

    for (int k0 = 0; k0 < 128; k0 += KC) {
        // --- stage A: relu + tf32, write in fragment order ---
        {
            int row = row0 + ar;
            float4 v0 = make_float4(0.f, 0.f, 0.f, 0.f);
            float4 v1 = make_float4(0.f, 0.f, 0.f, 0.f);
            if (row < NN) {
                v0 = *(const float4*)&g_h[row * DD + k0 + aks * 8];
                v1 = *(const float4*)&g_h[row * DD + k0 + aks * 8 + 4];
            }
            float f[8] = {fmaxf(v0.x, 0.f), fmaxf(v0.y, 0.f), fmaxf(v0.z, 0.f), fmaxf(v0.w, 0.f),
                          fmaxf(v1.x, 0.f), fmaxf(v1.y, 0.f), fmaxf(v1.z, 0.f), fmaxf(v1.w, 0.f)};
            uint32_t* dst = (uint32_t*)&AsF[amt * 2 + aks][0];
            #pragma unroll
            for (int j = 0; j < 8; j++) {
                int tig = j & 3, khi = j >> 2;
                int l = ag * 4 + tig;
                int reg = ahi8 + 2 * khi;
                dst[l * 4 + reg] = f2tf32(f[j]);
            }
        }
        // --- stage B: copy pre-split weights into fragment order ---
        {
            const uint32_t* sH = WHbase + (k0 + bk) * 256 + bc;
            const uint32_t* sL = WLbase + (k0 + bk) * 256 + bc;
            uint4 h0 = *(const uint4*)&sH[0];
            uint4 h1 = *(const uint4*)&sH[4];
            uint4 l0 = *(const uint4*)&sL[0];
            uint4 l1 = *(const uint4*)&sL[4];
            uint32_t hv[8] = {h0.x, h0.y, h0.z, h0.w, h1.x, h1.y, h1.z, h1.w};
            uint32_t lv[8] = {l0.x, l0.y, l0.z, l0.w, l1.x, l1.y, l1.z, l1.w};
            uint32_t* dH = (uint32_t*)&BsHF[bnt * 2 + bks][0];
            uint32_t* dL = (uint32_t*)&BsLF[bnt * 2 + bks][0];
            #pragma unroll
            for (int j = 0; j < 8; j++) {
                int l = j * 4 + btig;
                dH[l * 2 + bkhi] = hv[j];
                dL[l * 2 + bkhi] = lv[j];
            }
        }
        __syncthreads();

        #pragma unroll
        for (int ks = 0; ks < 2; ks++) {
            uint4 a[2];
            #pragma unroll
            for (int mi = 0; mi < 2; mi++)
                a[mi] = AsF[(wm * 2 + mi) * 2 + ks][lane];
            #pragma unroll
            for (int ni = 0; ni < 8; ni++) {
                uint2 bh = BsHF[(wn * 8 + ni) * 2 + ks][lane];
                uint2 bl = BsLF[(wn * 8 + ni) * 2 + ks][lane];
                #pragma unroll
                for (int mi = 0; mi < 2; mi++) {
                    mma_tf32(c[mi][ni], a[mi], bh.x, bh.y);
                    mma_tf32(c[mi][ni], a[mi], bl.x, bl.y);
                }
            }
        }
        __syncthreads();
    }

    // --- epilogue ---
    int g   = lane >> 2;
    int tig = lane & 3;
    const float* bias = yhalf ? br_ : bl_;
    float* dst = yhalf ? g_xr : g_xl;
    #pragma unroll
    for (int ni = 0; ni < 8; ni++) {
        int cn = wn * 64 + ni * 8 + tig * 2;
        float b0 = bias[cn], b1 = bias[cn + 1];
        #pragma unroll
        for (int mi = 0; mi < 2; mi++) {
            int ra = row0 + wm * 32 + mi * 16 + g;
            int rb = ra + 8;
            if (ra < NN)
                *(float2*)&dst[ra * DD + cn] = make_float2(c[mi][ni][0] + b0, c[mi][ni][1] + b1);
            if (rb < NN)
                *(float2*)&dst[rb * DD + cn] = make_float2(c[mi][ni][2] + b0, c[mi][ni][3] + b1);
        }
    }
}

// ---------------- attention v2: warp per node, 4 edges in parallel (8 lanes/edge) ----------------
__device__ __forceinline__ float dot_leaky(float4 c, float4 xr, float4 a, float d) {
    float v;
    v = c.x + xr.x; v = (v > 0.f) ? v : 0.2f * v; d = fmaf(v, a.x, d);
    v = c.y + xr.y; v = (v > 0.f) ? v : 0.2f * v; d = fmaf(v, a.y, d);
    v = c.z + xr.z; v = (v > 0.f) ? v : 0.2f * v; d = fmaf(v, a.z, d);
    v = c.w + xr.w; v = (v > 0.f) ? v : 0.2f * v; d = fmaf(v, a.w, d);
    return v, d;  // (comma op; returns d)
}

__global__ void attn(const float* __restrict__ avec, const float* __restrict__ bvec,
                     float* __restrict__ outp) {
    const unsigned FULL = 0xffffffffu;
    int w = (blockIdx.x * blockDim.x + threadIdx.x) >> 5;
    if (w >= NN) return;
    int lane = threadIdx.x & 31;
    int grp = lane >> 3;     // edge slot 0..3
    int sl  = lane & 7;      // dim slice
    int db  = sl * 16;       // dim base (16 floats per lane)

    const float* xrp = &g_xr[(size_t)w * DD + db];
    float4 xr0 = *(const float4*)&xrp[0];
    float4 xr1 = *(const float4*)&xrp[4];
    float4 xr2 = *(const float4*)&xrp[8];
    float4 xr3 = *(const float4*)&xrp[12];
    float4 a0 = *(const float4*)&avec[db];
    float4 a1 = *(const float4*)&avec[db + 4];
    float4 a2 = *(const float4*)&avec[db + 8];
    float4 a3 = *(const float4*)&avec[db + 12];

    int p = g_offs[w], end = g_offs[w + 1];
    float m = -1e30f, s = 0.f;
    float4 acc0 = make_float4(0, 0, 0, 0), acc1 = acc0, acc2 = acc0, acc3 = acc0;

    while (p < end) {
        int e = p + grp;
        int pe = (e < end) ? e : (end - 1);
        int src = g_srcs[pe];
        const float* xp = &g_xl[(size_t)src * DD + db];
        float4 c0 = *(const float4*)&xp[0];
        float4 c1 = *(const float4*)&xp[4];
        float4 c2 = *(const float4*)&xp[8];
        float4 c3 = *(const float4*)&xp[12];

        float d = 0.f, v;
        v = c0.x + xr0.x; v = (v > 0.f) ? v : 0.2f * v; d = fmaf(v, a0.x, d);
        v = c0.y + xr0.y; v = (v > 0.f) ? v : 0.2f * v; d = fmaf(v, a0.y, d);
        v = c0.z + xr0.z; v = (v > 0.f) ? v : 0.2f * v; d = fmaf(v, a0.z, d);
        v = c0.w + xr0.w; v = (v > 0.f) ? v : 0.2f * v; d = fmaf(v, a0.w, d);
        v = c1.x + xr1.x; v = (v > 0.f) ? v : 0.2f * v; d = fmaf(v, a1.x, d);
        v = c1.y + xr1.y; v = (v > 0.f) ? v : 0.2f * v; d = fmaf(v, a1.y, d);
        v = c1.z + xr1.z; v = (v > 0.f) ? v : 0.2f * v; d = fmaf(v, a1.z, d);
        v = c1.w + xr1.w; v = (v > 0.f) ? v : 0.2f * v; d = fmaf(v, a1.w, d);
        v = c2.x + xr2.x; v = (v > 0.f) ? v : 0.2f * v; d = fmaf(v, a2.x, d);
        v = c2.y + xr2.y; v = (v > 0.f) ? v : 0.2f * v; d = fmaf(v, a2.y, d);
        v = c2.z + xr2.z; v = (v > 0.f) ? v : 0.2f * v; d = fmaf(v, a2.z, d);
        v = c2.w + xr2.w; v = (v > 0.f) ? v : 0.2f * v; d = fmaf(v, a2.w, d);
        v = c3.x + xr3.x; v = (v > 0.f) ? v : 0.2f * v; d = fmaf(v, a3.x, d);
        v = c3.y + xr3.y; v = (v > 0.f) ? v : 0.2f * v; d = fmaf(v, a3.y, d);
        v = c3.z + xr3.z; v = (v > 0.f) ? v : 0.2f * v; d = fmaf(v, a3.z, d);
        v = c3.w + xr3.w; v = (v > 0.f) ? v : 0.2f * v; d = fmaf(v, a3.w, d);

        d += __shfl_xor_sync(FULL, d, 1);
        d += __shfl_xor_sync(FULL, d, 2);
        d += __shfl_xor_sync(FULL, d, 4);
        if (e >= end) d = -1e30f;

        float dg = d;
        dg = fmaxf(dg, __shfl_xor_sync(FULL, dg, 8));
        dg = fmaxf(dg, __shfl_xor_sync(FULL, dg, 16));
        float mn = fmaxf(m, dg);
        float sc  = __expf(m - mn);
        float wgt = __expf(d - mn);
        float sw = wgt;
        sw += __shfl_xor_sync(FULL, sw, 8);
        sw += __shfl_xor_sync(FULL, sw, 16);
        s = s * sc + sw;
        acc0.x = acc0.x * sc + wgt * c0.x; acc0.y = acc0.y * sc + wgt * c0.y;
        acc0.z = acc0.z * sc + wgt * c0.z; acc0.w = acc0.w * sc + wgt * c0.w;
        acc1.x = acc1.x * sc + wgt * c1.x; acc1.y = acc1.y * sc + wgt * c1.y;
        acc1.z = acc1.z * sc + wgt * c1.z; acc1.w = acc1.w * sc + wgt * c1.w;
        acc2.x = acc2.x * sc + wgt * c2.x; acc2.y = acc2.y * sc + wgt * c2.y;
        acc2.z = acc2.z * sc + wgt * c2.z; acc2.w = acc2.w * sc + wgt * c2.w;
        acc3.x = acc3.x * sc + wgt * c3.x; acc3.y = acc3.y * sc + wgt * c3.y;
        acc3.z = acc3.z * sc + wgt * c3.z; acc3.w = acc3.w * sc + wgt * c3.w;
        m = mn;
        p += 4;
    }

    // sum the 4 group replicas (same dims live at same sl across groups)
    #pragma unroll
    for (int st = 8; st <= 16; st <<= 1) {
        acc0.x += __shfl_xor_sync(FULL, acc0.x, st); acc0.y += __shfl_xor_sync(FULL, acc0.y, st);
        acc0.z += __shfl_xor_sync(FULL, acc0.z, st); acc0.w += __shfl_xor_sync(FULL, acc0.w, st);
        acc1.x += __shfl_xor_sync(FULL, acc1.x, st); acc1.y += __shfl_xor_sync(FULL, acc1.y, st);
        acc1.z += __shfl_xor_sync(FULL, acc1.z, st); acc1.w += __shfl_xor_sync(FULL, acc1.w, st);
        acc2.x += __shfl_xor_sync(FULL, acc2.x, st); acc2.y += __shfl_xor_sync(FULL, acc2.y, st);
        acc2.z += __shfl_xor_sync(FULL, acc2.z, st); acc2.w += __shfl_xor_sync(FULL, acc2.w, st);
        acc3.x += __shfl_xor_sync(FULL, acc3.x, st); acc3.y += __shfl_xor_sync(FULL, acc3.y, st);
        acc3.z += __shfl_xor_sync(FULL, acc3.z, st); acc3.w += __shfl_xor_sync(FULL, acc3.w, st);
    }

    float inv = 1.f / s;
    float4 av = (grp == 0) ? acc0 : (grp == 1) ? acc1 : (grp == 2) ? acc2 : acc3;
    float4 b4 = *(const float4*)&bvec[db + grp * 4];
    float* o = outp ? outp : g_h;
    float4 r = make_float4(av.x * inv + b4.x, av.y * inv + b4.y,
                           av.z * inv + b4.z, av.w * inv + b4.w);
    *(float4*)&o[(size_t)w * DD + db + grp * 4] = r;
}

// ---------------- launch ----------------
extern "C" void kernel_launch(void* const* d_in, const int* in_sizes, int n_in,
                              void* d_out, int out_size) {
    const float* x    = (const float*)d_in[0];
    const int*   ei   = (const int*)d_in[1];
    const float* Wl0  = (const float*)d_in[2];
    const float* Wr0  = (const float*)d_in[3];
    const float* bl0  = (const float*)d_in[4];
    const float* br0  = (const float*)d_in[5];
    const float* Wl   = (const float*)d_in[6];
    const float* Wr   = (const float*)d_in[7];
    const float* bl   = (const float*)d_in[8];
    const float* br   = (const float*)d_in[9];
    const float* att  = (const float*)d_in[10];
    const float* bias = (const float*)d_in[11];
    float* out = (float*)d_out;

    zero_counts<<<(NN + 255) / 256, 256>>>();
    count_edges<<<(ETOT + 255) / 256, 256>>>(ei);
    scan_block<<<NBSCAN, 256>>>();
    scan_spine<<<1, 32>>>();
    scan_fix<<<(NN + 255) / 256, 256>>>();
    fill_edges<<<(ETOT + 255) / 256, 256>>>(ei);
    split_w<<<(4 * 128 * 256 + 255) / 256, 256>>>(Wl, Wr);

    const int attn_blocks = (NN * 32 + 255) / 256;
    dim3 tc_grid((NN + 127) / 128, 2);

    gemm0<<<NN, 256>>>(x, Wl0, Wr0, bl0, br0);
    attn<<<attn_blocks, 256>>>(att, bias, nullptr);

    for (int t = 1; t < 5; t++) {
        gemm_tc<<<tc_grid, 256>>>(t - 1, bl + (size_t)(t - 1) * 128,
                                  br + (size_t)(t - 1) * 128);
        attn<<<attn_blocks, 256>>>(att + (size_t)t * 128, bias + (size_t)t * 128,
                                   (t == 4) ? out : nullptr);
    }
}

// round 5
// speedup vs baseline: 1.7310x; 1.7310x over previous
#include <cuda_runtime.h>
#include <cstdint>

#define NN 50000
#define EE 800000
#define ETOT (EE + NN)
#define DD 128
#define NBSCAN ((NN + 1023) / 1024)

// ---------------- static device scratch ----------------
__device__ float g_h[NN * DD];
__device__ float g_xl[NN * DD];
__device__ float g_xr[NN * DD];
__device__ int   g_deg[NN];
__device__ int   g_offs[NN + 1];
__device__ int   g_cur[NN];
__device__ int   g_srcs[ETOT];
__device__ int   g_bsums[NBSCAN];
// pre-split tf32 weights: [layer][k][col 0..255 = Wl|Wr]
__device__ uint32_t g_WH[4 * 128 * 256];
__device__ uint32_t g_WL[4 * 128 * 256];

__device__ __forceinline__ uint32_t f2tf32(float x) {
    uint32_t r;
    asm volatile("cvt.rna.tf32.f32 %0, %1;" : "=r"(r) : "f"(x));
    return r;
}

// ---------------- CSR build ----------------
__global__ void zero_counts() {
    int i = blockIdx.x * blockDim.x + threadIdx.x;
    if (i < NN) { g_deg[i] = 0; g_cur[i] = 0; }
}

__global__ void count_edges(const int* __restrict__ ei) {
    int t = blockIdx.x * blockDim.x + threadIdx.x;
    if (t < ETOT) {
        int dst = (t < EE) ? ei[EE + t] : (t - EE);
        atomicAdd(&g_deg[dst], 1);
    }
}

__global__ void scan_block() {
    __shared__ int sm[256];
    int t = threadIdx.x;
    int base = blockIdx.x * 1024 + t * 4;
    int v0 = (base + 0 < NN) ? g_deg[base + 0] : 0;
    int v1 = (base + 1 < NN) ? g_deg[base + 1] : 0;
    int v2 = (base + 2 < NN) ? g_deg[base + 2] : 0;
    int v3 = (base + 3 < NN) ? g_deg[base + 3] : 0;
    v1 += v0; v2 += v1; v3 += v2;
    sm[t] = v3;
    __syncthreads();
    #pragma unroll
    for (int off = 1; off < 256; off <<= 1) {
        int add = (t >= off) ? sm[t - off] : 0;
        __syncthreads();
        sm[t] += add;
        __syncthreads();
    }
    int prev = (t > 0) ? sm[t - 1] : 0;
    if (base + 0 < NN) g_offs[base + 0] = prev + v0;
    if (base + 1 < NN) g_offs[base + 1] = prev + v1;
    if (base + 2 < NN) g_offs[base + 2] = prev + v2;
    if (base + 3 < NN) g_offs[base + 3] = prev + v3;
    if (t == 255) g_bsums[blockIdx.x] = sm[255];
}

__global__ void scan_spine() {
    if (threadIdx.x == 0) {
        int acc = 0;
        for (int i = 0; i < NBSCAN; i++) { int v = g_bsums[i]; g_bsums[i] = acc; acc += v; }
    }
}

__global__ void scan_fix() {
    int i = blockIdx.x * blockDim.x + threadIdx.x;
    if (i < NN) g_offs[i] = g_offs[i] - g_deg[i] + g_bsums[i >> 10];
    if (i == 0) g_offs[NN] = ETOT;
}

__global__ void fill_edges(const int* __restrict__ ei) {
    int t = blockIdx.x * blockDim.x + threadIdx.x;
    if (t < ETOT) {
        int src, dst;
        if (t < EE) { src = ei[t]; dst = ei[EE + t]; }
        else        { src = t - EE; dst = src; }
        int pos = g_offs[dst] + atomicAdd(&g_cur[dst], 1);
        g_srcs[pos] = src;
    }
}

// ---------------- weight pre-split ----------------
__global__ void split_w(const float* __restrict__ Wl, const float* __restrict__ Wr) {
    int i = blockIdx.x * blockDim.x + threadIdx.x;
    if (i >= 4 * 128 * 256) return;
    int layer = i >> 15;
    int rem = i & 32767;
    int k = rem >> 8;
    int c = rem & 255;
    float v = (c < 128) ? Wl[layer * 16384 + k * 128 + c]
                        : Wr[layer * 16384 + k * 128 + (c - 128)];
    uint32_t hi = f2tf32(v);
    float lo = v - __uint_as_float(hi);
    g_WH[i] = hi;
    g_WL[i] = f2tf32(lo);
}

// ---------------- layer 0 GEMM (K=7) ----------------
__global__ void gemm0(const float* __restrict__ x,
                      const float* __restrict__ Wl0, const float* __restrict__ Wr0,
                      const float* __restrict__ bl0, const float* __restrict__ br0) {
    int node = blockIdx.x;
    int j = threadIdx.x;
    __shared__ float xs[7];
    if (j < 7) xs[j] = x[node * 7 + j];
    __syncthreads();
    const float* W = (j < 128) ? Wl0 : Wr0;
    int c = j & 127;
    float acc = (j < 128) ? bl0[c] : br0[c];
    #pragma unroll
    for (int k = 0; k < 7; k++) acc += xs[k] * W[k * 128 + c];
    if (j < 128) g_xl[node * DD + c] = acc;
    else         g_xr[node * DD + c] = acc;
}

// ---------------- TC GEMM v3: A=tf32 (single), B=tf32 hi/lo, 2 MMAs/tile ----------------
// Grid (ceil(N/128), 2): y=0 -> Wl -> g_xl, y=1 -> Wr -> g_xr.
// Block tile 128x128, 8 warps (wm 0..3, wn 0..1), warp tile 32x64 = 2 m16 x 8 n8.
#define KC 16

__device__ __forceinline__ void mma_tf32(float c[4], const uint32_t a[4], uint32_t b0, uint32_t b1) {
    asm volatile(
        "mma.sync.aligned.m16n8k8.row.col.f32.tf32.tf32.f32 "
        "{%0,%1,%2,%3}, {%4,%5,%6,%7}, {%8,%9}, {%0,%1,%2,%3};"
        : "+f"(c[0]), "+f"(c[1]), "+f"(c[2]), "+f"(c[3])
        : "r"(a[0]), "r"(a[1]), "r"(a[2]), "r"(a[3]), "r"(b0), "r"(b1));
}

__global__ __launch_bounds__(256, 2) void gemm_tc(int layer,
                                                  const float* __restrict__ bl_,
                                                  const float* __restrict__ br_) {
    __shared__ uint32_t As[128][20];                  // [row][k], pad 16->20 (conflict-free)
    __shared__ uint32_t BsH[KC][136], BsL[KC][136];   // [k][col], pad 128->136 (conflict-free)

    int tid  = threadIdx.x;
    int lane = tid & 31;
    int wid  = tid >> 5;
    int g    = lane >> 2;
    int tig  = lane & 3;
    int wm   = wid >> 1;        // 0..3
    int wn   = wid & 1;         // 0..1
    int m_base = wm * 32;
    int n_base = wn * 64;
    int row0 = blockIdx.x * 128;
    int yhalf = blockIdx.y;

    const uint32_t* WHbase = g_WH + layer * 32768 + yhalf * 128;
    const uint32_t* WLbase = g_WL + layer * 32768 + yhalf * 128;

    float c[2][8][4];
    #pragma unroll
    for (int mi = 0; mi < 2; mi++)
        #pragma unroll
        for (int ni = 0; ni < 8; ni++)
            #pragma unroll
            for (int q = 0; q < 4; q++) c[mi][ni][q] = 0.f;

    int ar  = tid >> 1;                 // A stage: row 0..127
    int akq = (tid & 1) * 8;            // A stage: k offset (8 wide)
    int bk  = tid >> 4;                 // B stage: k (0..15)
    int bc  = (tid & 15) * 8;           // B stage: col offset (8 wide)

    for (int k0 = 0; k0 < 128; k0 += KC) {
        // --- stage A: relu + single tf32 ---
        {
            int row = row0 + ar;
            float4 v0 = make_float4(0.f, 0.f, 0.f, 0.f);
            float4 v1 = make_float4(0.f, 0.f, 0.f, 0.f);
            if (row < NN) {
                v0 = *(const float4*)&g_h[row * DD + k0 + akq];
                v1 = *(const float4*)&g_h[row * DD + k0 + akq + 4];
            }
            float f[8] = {fmaxf(v0.x, 0.f), fmaxf(v0.y, 0.f), fmaxf(v0.z, 0.f), fmaxf(v0.w, 0.f),
                          fmaxf(v1.x, 0.f), fmaxf(v1.y, 0.f), fmaxf(v1.z, 0.f), fmaxf(v1.w, 0.f)};
            #pragma unroll
            for (int j = 0; j < 8; j++) As[ar][akq + j] = f2tf32(f[j]);
        }
        // --- stage B: pure copy of pre-split weights ---
        {
            const uint32_t* sH = WHbase + (k0 + bk) * 256 + bc;
            const uint32_t* sL = WLbase + (k0 + bk) * 256 + bc;
            *(uint4*)&BsH[bk][bc]     = *(const uint4*)&sH[0];
            *(uint4*)&BsH[bk][bc + 4] = *(const uint4*)&sH[4];
            *(uint4*)&BsL[bk][bc]     = *(const uint4*)&sL[0];
            *(uint4*)&BsL[bk][bc + 4] = *(const uint4*)&sL[4];
        }
        __syncthreads();

        #pragma unroll
        for (int ks = 0; ks < KC; ks += 8) {
            uint32_t a[2][4];
            #pragma unroll
            for (int mi = 0; mi < 2; mi++) {
                int r = m_base + mi * 16 + g;
                a[mi][0] = As[r][ks + tig];
                a[mi][1] = As[r + 8][ks + tig];
                a[mi][2] = As[r][ks + tig + 4];
                a[mi][3] = As[r + 8][ks + tig + 4];
            }
            #pragma unroll
            for (int ni = 0; ni < 8; ni++) {
                int cc = n_base + ni * 8 + g;
                uint32_t bH0 = BsH[ks + tig][cc],     bL0 = BsL[ks + tig][cc];
                uint32_t bH1 = BsH[ks + tig + 4][cc], bL1 = BsL[ks + tig + 4][cc];
                #pragma unroll
                for (int mi = 0; mi < 2; mi++) {
                    mma_tf32(c[mi][ni], a[mi], bH0, bH1);
                    mma_tf32(c[mi][ni], a[mi], bL0, bL1);
                }
            }
        }
        __syncthreads();
    }

    // --- epilogue ---
    const float* bias = yhalf ? br_ : bl_;
    float* dst = yhalf ? g_xr : g_xl;
    #pragma unroll
    for (int ni = 0; ni < 8; ni++) {
        int cn = n_base + ni * 8 + tig * 2;
        float b0 = bias[cn], b1 = bias[cn + 1];
        #pragma unroll
        for (int mi = 0; mi < 2; mi++) {
            int ra = row0 + m_base + mi * 16 + g;
            int rb = ra + 8;
            if (ra < NN)
                *(float2*)&dst[ra * DD + cn] = make_float2(c[mi][ni][0] + b0, c[mi][ni][1] + b1);
            if (rb < NN)
                *(float2*)&dst[rb * DD + cn] = make_float2(c[mi][ni][2] + b0, c[mi][ni][3] + b1);
        }
    }
}

// ---------------- attention (r1/r3 proven version): warp per node, online softmax ----------------
__global__ void attn(const float* __restrict__ avec, const float* __restrict__ bvec,
                     float* __restrict__ outp) {
    const unsigned FULL = 0xffffffffu;
    int w = (blockIdx.x * blockDim.x + threadIdx.x) >> 5;
    if (w >= NN) return;
    int lane = threadIdx.x & 31;

    float4 xr4 = *(float4*)&g_xr[w * DD + lane * 4];
    float4 a4  = *(const float4*)&avec[lane * 4];

    int p = g_offs[w], end = g_offs[w + 1];
    float m = -1e30f, s = 0.f;
    float ax = 0.f, ay = 0.f, az = 0.f, aw = 0.f;

    int src = g_srcs[p];
    float4 xl4 = *(float4*)&g_xl[src * DD + lane * 4];

    while (p < end) {
        float4 cur = xl4;
        int pn = p + 1;
        if (pn < end) {
            int s2 = g_srcs[pn];
            xl4 = *(float4*)&g_xl[s2 * DD + lane * 4];
        }
        float vx = cur.x + xr4.x; vx = (vx > 0.f) ? vx : 0.2f * vx;
        float vy = cur.y + xr4.y; vy = (vy > 0.f) ? vy : 0.2f * vy;
        float vz = cur.z + xr4.z; vz = (vz > 0.f) ? vz : 0.2f * vz;
        float vw = cur.w + xr4.w; vw = (vw > 0.f) ? vw : 0.2f * vw;
        float d = vx * a4.x + vy * a4.y + vz * a4.z + vw * a4.w;
        d += __shfl_xor_sync(FULL, d, 16);
        d += __shfl_xor_sync(FULL, d, 8);
        d += __shfl_xor_sync(FULL, d, 4);
        d += __shfl_xor_sync(FULL, d, 2);
        d += __shfl_xor_sync(FULL, d, 1);

        float mn  = fmaxf(m, d);
        float sc  = __expf(m - mn);
        float wgt = __expf(d - mn);
        s  = s * sc + wgt;
        ax = ax * sc + wgt * cur.x;
        ay = ay * sc + wgt * cur.y;
        az = az * sc + wgt * cur.z;
        aw = aw * sc + wgt * cur.w;
        m = mn;
        p = pn;
    }

    float inv = 1.f / s;
    float4 b4 = *(const float4*)&bvec[lane * 4];
    float* o = outp ? outp : g_h;
    float4 r = make_float4(ax * inv + b4.x, ay * inv + b4.y,
                           az * inv + b4.z, aw * inv + b4.w);
    *(float4*)&o[w * DD + lane * 4] = r;
}

// ---------------- launch ----------------
extern "C" void kernel_launch(void* const* d_in, const int* in_sizes, int n_in,
                              void* d_out, int out_size) {
    const float* x    = (const float*)d_in[0];
    const int*   ei   = (const int*)d_in[1];
    const float* Wl0  = (const float*)d_in[2];
    const float* Wr0  = (const float*)d_in[3];
    const float* bl0  = (const float*)d_in[4];
    const float* br0  = (const float*)d_in[5];
    const float* Wl   = (const float*)d_in[6];
    const float* Wr   = (const float*)d_in[7];
    const float* bl   = (const float*)d_in[8];
    const float* br   = (const float*)d_in[9];
    const float* att  = (const float*)d_in[10];
    const float* bias = (const float*)d_in[11];
    float* out = (float*)d_out;

    zero_counts<<<(NN + 255) / 256, 256>>>();
    count_edges<<<(ETOT + 255) / 256, 256>>>(ei);
    scan_block<<<NBSCAN, 256>>>();
    scan_spine<<<1, 32>>>();
    scan_fix<<<(NN + 255) / 256, 256>>>();
    fill_edges<<<(ETOT + 255) / 256, 256>>>(ei);
    split_w<<<(4 * 128 * 256 + 255) / 256, 256>>>(Wl, Wr);

    const int attn_blocks = (NN * 32 + 255) / 256;
    dim3 tc_grid((NN + 127) / 128, 2);

    gemm0<<<NN, 256>>>(x, Wl0, Wr0, bl0, br0);
    attn<<<attn_blocks, 256>>>(att, bias, nullptr);

    for (int t = 1; t < 5; t++) {
        gemm_tc<<<tc_grid, 256>>>(t - 1, bl + (size_t)(t - 1) * 128,
                                  br + (size_t)(t - 1) * 128);
        attn<<<attn_blocks, 256>>>(att + (size_t)t * 128, bias + (size_t)t * 128,
                                   (t == 4) ? out : nullptr);
    }
}

// round 6
// speedup vs baseline: 1.8022x; 1.0411x over previous
#include <cuda_runtime.h>
#include <cstdint>

#define NN 50000
#define EE 800000
#define ETOT (EE + NN)
#define DD 128
#define NBSCAN ((NN + 1023) / 1024)

// ---------------- static device scratch ----------------
__device__ float g_h[NN * DD];
__device__ float g_xl[NN * DD];
__device__ float g_xr[NN * DD];
__device__ int   g_deg[NN];
__device__ int   g_offs[NN + 1];
__device__ int   g_cur[NN];
__device__ int   g_srcs[ETOT];
__device__ int   g_bsums[NBSCAN];
// pre-split tf32 weights: [layer][k][col 0..255 = Wl|Wr]
__device__ uint32_t g_WH[4 * 128 * 256];
__device__ uint32_t g_WL[4 * 128 * 256];

__device__ __forceinline__ uint32_t f2tf32(float x) {
    uint32_t r;
    asm volatile("cvt.rna.tf32.f32 %0, %1;" : "=r"(r) : "f"(x));
    return r;
}

// ---------------- CSR build ----------------
__global__ void zero_counts() {
    int i = blockIdx.x * blockDim.x + threadIdx.x;
    if (i < NN) { g_deg[i] = 0; g_cur[i] = 0; }
}

__global__ void count_edges(const int* __restrict__ ei) {
    int t = blockIdx.x * blockDim.x + threadIdx.x;
    if (t < ETOT) {
        int dst = (t < EE) ? ei[EE + t] : (t - EE);
        atomicAdd(&g_deg[dst], 1);
    }
}

__global__ void scan_block() {
    __shared__ int sm[256];
    int t = threadIdx.x;
    int base = blockIdx.x * 1024 + t * 4;
    int v0 = (base + 0 < NN) ? g_deg[base + 0] : 0;
    int v1 = (base + 1 < NN) ? g_deg[base + 1] : 0;
    int v2 = (base + 2 < NN) ? g_deg[base + 2] : 0;
    int v3 = (base + 3 < NN) ? g_deg[base + 3] : 0;
    v1 += v0; v2 += v1; v3 += v2;
    sm[t] = v3;
    __syncthreads();
    #pragma unroll
    for (int off = 1; off < 256; off <<= 1) {
        int add = (t >= off) ? sm[t - off] : 0;
        __syncthreads();
        sm[t] += add;
        __syncthreads();
    }
    int prev = (t > 0) ? sm[t - 1] : 0;
    if (base + 0 < NN) g_offs[base + 0] = prev + v0;
    if (base + 1 < NN) g_offs[base + 1] = prev + v1;
    if (base + 2 < NN) g_offs[base + 2] = prev + v2;
    if (base + 3 < NN) g_offs[base + 3] = prev + v3;
    if (t == 255) g_bsums[blockIdx.x] = sm[255];
}

__global__ void scan_spine() {
    if (threadIdx.x == 0) {
        int acc = 0;
        for (int i = 0; i < NBSCAN; i++) { int v = g_bsums[i]; g_bsums[i] = acc; acc += v; }
    }
}

__global__ void scan_fix() {
    int i = blockIdx.x * blockDim.x + threadIdx.x;
    if (i < NN) g_offs[i] = g_offs[i] - g_deg[i] + g_bsums[i >> 10];
    if (i == 0) g_offs[NN] = ETOT;
}

__global__ void fill_edges(const int* __restrict__ ei) {
    int t = blockIdx.x * blockDim.x + threadIdx.x;
    if (t < ETOT) {
        int src, dst;
        if (t < EE) { src = ei[t]; dst = ei[EE + t]; }
        else        { src = t - EE; dst = src; }
        int pos = g_offs[dst] + atomicAdd(&g_cur[dst], 1);
        g_srcs[pos] = src;
    }
}

// ---------------- weight pre-split ----------------
__global__ void split_w(const float* __restrict__ Wl, const float* __restrict__ Wr) {
    int i = blockIdx.x * blockDim.x + threadIdx.x;
    if (i >= 4 * 128 * 256) return;
    int layer = i >> 15;
    int rem = i & 32767;
    int k = rem >> 8;
    int c = rem & 255;
    float v = (c < 128) ? Wl[layer * 16384 + k * 128 + c]
                        : Wr[layer * 16384 + k * 128 + (c - 128)];
    uint32_t hi = f2tf32(v);
    float lo = v - __uint_as_float(hi);
    g_WH[i] = hi;
    g_WL[i] = f2tf32(lo);
}

// ---------------- layer 0 GEMM (K=7) ----------------
__global__ void gemm0(const float* __restrict__ x,
                      const float* __restrict__ Wl0, const float* __restrict__ Wr0,
                      const float* __restrict__ bl0, const float* __restrict__ br0) {
    int node = blockIdx.x;
    int j = threadIdx.x;
    __shared__ float xs[7];
    if (j < 7) xs[j] = x[node * 7 + j];
    __syncthreads();
    const float* W = (j < 128) ? Wl0 : Wr0;
    int c = j & 127;
    float acc = (j < 128) ? bl0[c] : br0[c];
    #pragma unroll
    for (int k = 0; k < 7; k++) acc += xs[k] * W[k * 128 + c];
    if (j < 128) g_xl[node * DD + c] = acc;
    else         g_xr[node * DD + c] = acc;
}

// ---------------- TC GEMM v4: double-buffered, cp.async B, A=tf32, B=hi/lo ----------------
// Grid (ceil(N/128), 2): y=0 -> Wl -> g_xl, y=1 -> Wr -> g_xr.
// Block tile 128x128, 8 warps (wm 0..3, wn 0..1), warp tile 32x64.
#define KC 16
// per-stage word layout: As [128][20] = 2560 | BsH [16][136] = 2176 | BsL = 2176
#define STAGE_WORDS 6912
#define OFF_BH 2560
#define OFF_BL 4736
#define GEMM_SMEM_BYTES (2 * STAGE_WORDS * 4)

__device__ __forceinline__ void mma_tf32(float c[4], const uint32_t a[4], uint32_t b0, uint32_t b1) {
    asm volatile(
        "mma.sync.aligned.m16n8k8.row.col.f32.tf32.tf32.f32 "
        "{%0,%1,%2,%3}, {%4,%5,%6,%7}, {%8,%9}, {%0,%1,%2,%3};"
        : "+f"(c[0]), "+f"(c[1]), "+f"(c[2]), "+f"(c[3])
        : "r"(a[0]), "r"(a[1]), "r"(a[2]), "r"(a[3]), "r"(b0), "r"(b1));
}

__device__ __forceinline__ void cp16(uint32_t* dst_smem, const uint32_t* src_gmem) {
    uint32_t saddr = (uint32_t)__cvta_generic_to_shared(dst_smem);
    asm volatile("cp.async.cg.shared.global [%0], [%1], 16;" :: "r"(saddr), "l"(src_gmem));
}

__global__ __launch_bounds__(256, 2) void gemm_tc(int layer,
                                                  const float* __restrict__ bl_,
                                                  const float* __restrict__ br_) {
    extern __shared__ uint32_t smem[];

    int tid  = threadIdx.x;
    int lane = tid & 31;
    int wid  = tid >> 5;
    int g    = lane >> 2;
    int tig  = lane & 3;
    int wm   = wid >> 1;        // 0..3
    int wn   = wid & 1;         // 0..1
    int m_base = wm * 32;
    int n_base = wn * 64;
    int row0 = blockIdx.x * 128;
    int yhalf = blockIdx.y;

    const uint32_t* WHbase = g_WH + layer * 32768 + yhalf * 128;
    const uint32_t* WLbase = g_WL + layer * 32768 + yhalf * 128;

    float c[2][8][4];
    #pragma unroll
    for (int mi = 0; mi < 2; mi++)
        #pragma unroll
        for (int ni = 0; ni < 8; ni++)
            #pragma unroll
            for (int q = 0; q < 4; q++) c[mi][ni][q] = 0.f;

    int ar  = tid >> 1;                 // A stage: row 0..127
    int akq = (tid & 1) * 8;            // A stage: k offset (8 wide)
    int bk  = tid >> 4;                 // B stage: k (0..15)
    int bc  = (tid & 15) * 8;           // B stage: col offset (8 wide)
    int arow = row0 + ar;
    bool a_ok = (arow < NN);
    const float* a_gp = &g_h[(size_t)arow * DD + akq];

    // ---- prologue: A(0) -> regs, B(0) -> stage 0 via cp.async ----
    float4 fa0 = make_float4(0.f, 0.f, 0.f, 0.f);
    float4 fa1 = make_float4(0.f, 0.f, 0.f, 0.f);
    if (a_ok) {
        fa0 = *(const float4*)&a_gp[0];
        fa1 = *(const float4*)&a_gp[4];
    }
    {
        uint32_t* BH = smem + OFF_BH;
        uint32_t* BL = smem + OFF_BL;
        const uint32_t* sH = WHbase + bk * 256 + bc;
        const uint32_t* sL = WLbase + bk * 256 + bc;
        cp16(&BH[bk * 136 + bc],     &sH[0]);
        cp16(&BH[bk * 136 + bc + 4], &sH[4]);
        cp16(&BL[bk * 136 + bc],     &sL[0]);
        cp16(&BL[bk * 136 + bc + 4], &sL[4]);
        asm volatile("cp.async.commit_group;");
    }

    for (int it = 0; it < 8; it++) {
        int cur = it & 1;
        uint32_t* As  = smem + cur * STAGE_WORDS;
        uint32_t* BsH = As + OFF_BH;
        uint32_t* BsL = As + OFF_BL;

        // STS A(it) from regs (relu + tf32)
        {
            float f[8] = {fmaxf(fa0.x, 0.f), fmaxf(fa0.y, 0.f), fmaxf(fa0.z, 0.f), fmaxf(fa0.w, 0.f),
                          fmaxf(fa1.x, 0.f), fmaxf(fa1.y, 0.f), fmaxf(fa1.z, 0.f), fmaxf(fa1.w, 0.f)};
            #pragma unroll
            for (int j = 0; j < 8; j++) As[ar * 20 + akq + j] = f2tf32(f[j]);
        }
        // B(it) must have landed
        asm volatile("cp.async.wait_group 0;");
        __syncthreads();
        // after this barrier: everyone done reading stage (it-1) -> safe to fill it
        if (it < 7) {
            int k0n = (it + 1) * KC;
            if (a_ok) {
                fa0 = *(const float4*)&a_gp[k0n];
                fa1 = *(const float4*)&a_gp[k0n + 4];
            }
            uint32_t* An  = smem + ((it + 1) & 1) * STAGE_WORDS;
            uint32_t* BHn = An + OFF_BH;
            uint32_t* BLn = An + OFF_BL;
            const uint32_t* sH = WHbase + (k0n + bk) * 256 + bc;
            const uint32_t* sL = WLbase + (k0n + bk) * 256 + bc;
            cp16(&BHn[bk * 136 + bc],     &sH[0]);
            cp16(&BHn[bk * 136 + bc + 4], &sH[4]);
            cp16(&BLn[bk * 136 + bc],     &sL[0]);
            cp16(&BLn[bk * 136 + bc + 4], &sL[4]);
            asm volatile("cp.async.commit_group;");
        }

        // compute on stage cur (overlaps the async copies above)
        #pragma unroll
        for (int ks = 0; ks < KC; ks += 8) {
            uint32_t a[2][4];
            #pragma unroll
            for (int mi = 0; mi < 2; mi++) {
                int r = m_base + mi * 16 + g;
                a[mi][0] = As[r * 20 + ks + tig];
                a[mi][1] = As[(r + 8) * 20 + ks + tig];
                a[mi][2] = As[r * 20 + ks + tig + 4];
                a[mi][3] = As[(r + 8) * 20 + ks + tig + 4];
            }
            #pragma unroll
            for (int ni = 0; ni < 8; ni++) {
                int cc = n_base + ni * 8 + g;
                uint32_t bH0 = BsH[(ks + tig) * 136 + cc],     bL0 = BsL[(ks + tig) * 136 + cc];
                uint32_t bH1 = BsH[(ks + tig + 4) * 136 + cc], bL1 = BsL[(ks + tig + 4) * 136 + cc];
                #pragma unroll
                for (int mi = 0; mi < 2; mi++) {
                    mma_tf32(c[mi][ni], a[mi], bH0, bH1);
                    mma_tf32(c[mi][ni], a[mi], bL0, bL1);
                }
            }
        }
        __syncthreads();
    }

    // --- epilogue ---
    const float* bias = yhalf ? br_ : bl_;
    float* dst = yhalf ? g_xr : g_xl;
    #pragma unroll
    for (int ni = 0; ni < 8; ni++) {
        int cn = n_base + ni * 8 + tig * 2;
        float b0 = bias[cn], b1 = bias[cn + 1];
        #pragma unroll
        for (int mi = 0; mi < 2; mi++) {
            int ra = row0 + m_base + mi * 16 + g;
            int rb = ra + 8;
            if (ra < NN)
                *(float2*)&dst[ra * DD + cn] = make_float2(c[mi][ni][0] + b0, c[mi][ni][1] + b1);
            if (rb < NN)
                *(float2*)&dst[rb * DD + cn] = make_float2(c[mi][ni][2] + b0, c[mi][ni][3] + b1);
        }
    }
}

// ---------------- attention (unchanged control): warp per node, online softmax ----------------
__global__ void attn(const float* __restrict__ avec, const float* __restrict__ bvec,
                     float* __restrict__ outp) {
    const unsigned FULL = 0xffffffffu;
    int w = (blockIdx.x * blockDim.x + threadIdx.x) >> 5;
    if (w >= NN) return;
    int lane = threadIdx.x & 31;

    float4 xr4 = *(float4*)&g_xr[w * DD + lane * 4];
    float4 a4  = *(const float4*)&avec[lane * 4];

    int p = g_offs[w], end = g_offs[w + 1];
    float m = -1e30f, s = 0.f;
    float ax = 0.f, ay = 0.f, az = 0.f, aw = 0.f;

    int src = g_srcs[p];
    float4 xl4 = *(float4*)&g_xl[src * DD + lane * 4];

    while (p < end) {
        float4 cur = xl4;
        int pn = p + 1;
        if (pn < end) {
            int s2 = g_srcs[pn];
            xl4 = *(float4*)&g_xl[s2 * DD + lane * 4];
        }
        float vx = cur.x + xr4.x; vx = (vx > 0.f) ? vx : 0.2f * vx;
        float vy = cur.y + xr4.y; vy = (vy > 0.f) ? vy : 0.2f * vy;
        float vz = cur.z + xr4.z; vz = (vz > 0.f) ? vz : 0.2f * vz;
        float vw = cur.w + xr4.w; vw = (vw > 0.f) ? vw : 0.2f * vw;
        float d = vx * a4.x + vy * a4.y + vz * a4.z + vw * a4.w;
        d += __shfl_xor_sync(FULL, d, 16);
        d += __shfl_xor_sync(FULL, d, 8);
        d += __shfl_xor_sync(FULL, d, 4);
        d += __shfl_xor_sync(FULL, d, 2);
        d += __shfl_xor_sync(FULL, d, 1);

        float mn  = fmaxf(m, d);
        float sc  = __expf(m - mn);
        float wgt = __expf(d - mn);
        s  = s * sc + wgt;
        ax = ax * sc + wgt * cur.x;
        ay = ay * sc + wgt * cur.y;
        az = az * sc + wgt * cur.z;
        aw = aw * sc + wgt * cur.w;
        m = mn;
        p = pn;
    }

    float inv = 1.f / s;
    float4 b4 = *(const float4*)&bvec[lane * 4];
    float* o = outp ? outp : g_h;
    float4 r = make_float4(ax * inv + b4.x, ay * inv + b4.y,
                           az * inv + b4.z, aw * inv + b4.w);
    *(float4*)&o[w * DD + lane * 4] = r;
}

// ---------------- launch ----------------
extern "C" void kernel_launch(void* const* d_in, const int* in_sizes, int n_in,
                              void* d_out, int out_size) {
    const float* x    = (const float*)d_in[0];
    const int*   ei   = (const int*)d_in[1];
    const float* Wl0  = (const float*)d_in[2];
    const float* Wr0  = (const float*)d_in[3];
    const float* bl0  = (const float*)d_in[4];
    const float* br0  = (const float*)d_in[5];
    const float* Wl   = (const float*)d_in[6];
    const float* Wr   = (const float*)d_in[7];
    const float* bl   = (const float*)d_in[8];
    const float* br   = (const float*)d_in[9];
    const float* att  = (const float*)d_in[10];
    const float* bias = (const float*)d_in[11];
    float* out = (float*)d_out;

    cudaFuncSetAttribute(gemm_tc, cudaFuncAttributeMaxDynamicSharedMemorySize, GEMM_SMEM_BYTES);

    zero_counts<<<(NN + 255) / 256, 256>>>();
    count_edges<<<(ETOT + 255) / 256, 256>>>(ei);
    scan_block<<<NBSCAN, 256>>>();
    scan_spine<<<1, 32>>>();
    scan_fix<<<(NN + 255) / 256, 256>>>();
    fill_edges<<<(ETOT + 255) / 256, 256>>>(ei);
    split_w<<<(4 * 128 * 256 + 255) / 256, 256>>>(Wl, Wr);

    const int attn_blocks = (NN * 32 + 255) / 256;
    dim3 tc_grid((NN + 127) / 128, 2);

    gemm0<<<NN, 256>>>(x, Wl0, Wr0, bl0, br0);
    attn<<<attn_blocks, 256>>>(att, bias, nullptr);

    for (int t = 1; t < 5; t++) {
        gemm_tc<<<tc_grid, 256, GEMM_SMEM_BYTES>>>(t - 1, bl + (size_t)(t - 1) * 128,
                                                   br + (size_t)(t - 1) * 128);
        attn<<<attn_blocks, 256>>>(att + (size_t)t * 128, bias + (size_t)t * 128,
                                   (t == 4) ? out : nullptr);
    }
}